// round 6
// baseline (speedup 1.0000x reference)
#include <cuda_runtime.h>
#include <cuda_bf16.h>
#include <math.h>

// ---------------------------------------------------------------------------
// Problem constants
// ---------------------------------------------------------------------------
#define G_      16
#define C_      4
#define R_      64
#define MUL_    128
#define KDIM    36          // (LMAX+1)^2
#define RB      180
#define RA      359
#define NPIX    (RB*RA)     // 64620
#define NPIX4   (NPIX/4)    // 16155
#define EMB     4608
#define NIRR    768
#define MDIM    12          // 11 signed-m slots (m=-5..5) + 1 pad

#define RSQRT_MUL 0.08838834764831845f   // 1/sqrt(128)
#define RSQRT_RAD 0.125f                 // 1/sqrt(64)
#define B0C       0.28209479177387814f   // Y00 = 1/sqrt(4*pi)
#define PI_F      3.14159265358979323846f
#define FOURPI_F  12.566370614359172f

// output layout: concat of the 4 returned tensors, flattened, in order
#define OFF_LPC  0
#define OFF_POS  147456                          // 16*4*64*36
#define OFF_ANG  (OFF_POS + 66170880)            // + 16*64*64620
#define OFF_RAD  (OFF_ANG + 1033920)             // + 16*64620

#define BAR_FRONT() asm volatile("bar.sync 1, 128;" ::: "memory")

__device__ __forceinline__ int lofk(int k) {
    const int t[36] = {0,1,1,1,2,2,2,2,2,3,3,3,3,3,3,3,
                       4,4,4,4,4,4,4,4,4,5,5,5,5,5,5,5,5,5,5,5};
    return t[k];
}

// ---------------------------------------------------------------------------
// Single fused kernel. Block = (pixel-tile, graph). 256 threads.
// Prologue (team-split):
//   warps 0-3 (tid 0..127): front section for graph g (gather, species scale,
//     radial MLP, angular projection) -> smem; blockIdx.x==0 blocks also emit
//     log_position_coeffs + radial_logits. Synced with bar.sync 1,128.
//   warp 4 lanes 0-3 (tid 128..131): Gauss-Legendre root + normalized assoc.
//     Legendre row F[b0+row][36] -> smem (float-only Newton, table-driven).
// Then m-separation into A[4][C][12], then the write-streaming pixel loop.
// ---------------------------------------------------------------------------
__global__ void __launch_bounds__(256) k_all(
        const float* __restrict__ emb, const float* __restrict__ spec,
        const float* __restrict__ Wr, const float* __restrict__ Wm1,
        const float* __restrict__ Wm2,
        const float* __restrict__ Wa0, const float* __restrict__ Wa1,
        const float* __restrict__ Wa2, const float* __restrict__ Wa3,
        const float* __restrict__ Wa4, const float* __restrict__ Wa5,
        const int* __restrict__ focus, const int* __restrict__ tspec,
        float* __restrict__ out) {
    // s_A is read via float4 -> must be 16B aligned (R5 fault: it inherited
    // an 8-mod-16 offset from preceding smem arrays).
    __shared__ __align__(16) float s_A[4][C_][MDIM];   // m-separated coeffs
    __shared__ __align__(16) float s_F[4][KDIM];       // beta rows b0..b0+3
    __shared__ float sca[RB + 1], scb[RB + 1];     // Legendre recurrence tables
    __shared__ float s_sc[KDIM][MUL_ + 1];         // species-scaled irreps
    __shared__ float s_r[64];
    __shared__ float s_h[128];
    __shared__ float s_radRaw[R_];
    __shared__ float s_radB[R_];
    __shared__ float s_ang[C_][KDIM];

    const int g   = blockIdx.y;
    const int p0  = blockIdx.x * 256;
    const int b0  = (4 * p0) / RA;
    const int tid = threadIdx.x;

    // Legendre recurrence coefficient tables (divide-free serial chain later)
    for (int k = 2 + tid; k <= RB; k += 256) {
        sca[k] = (float)((2.0 * k - 1.0) / (double)k);
        scb[k] = (float)((k - 1.0) / (double)k);
    }
    __syncthreads();

    if (tid < 128) {
        // ----- FRONT TEAM (warps 0-3), barriers: bar.sync 1,128 -----
        const int u = tid;
        const float* f  = emb  + (size_t)focus[g] * EMB;
        const float* sp = spec + (size_t)tspec[g] * NIRR;

        #pragma unroll
        for (int l = 0; l <= 5; l++) {
            float s = sp[128*l + u];
            int d = 2*l + 1;
            const float* fb = f + 128*l*l + u*d;
            for (int m = 0; m < d; m++) s_sc[l*l + m][u] = fb[m] * s;
        }
        BAR_FRONT();

        if (u < 64) {
            float acc = 0.f;
            #pragma unroll 8
            for (int v = 0; v < 128; v++) acc += s_sc[0][v] * Wr[v*64 + u];
            s_r[u] = acc * RSQRT_MUL;
        }
        BAR_FRONT();

        {
            float acc = 0.f;
            #pragma unroll 8
            for (int j = 0; j < 64; j++) acc += s_r[j] * Wm1[j*128 + u];
            acc *= RSQRT_RAD;
            s_h[u] = fmaxf(acc, 0.f) + log1pf(expf(-fabsf(acc)));
        }
        BAR_FRONT();

        if (u < 64) {
            float acc = 0.f;
            #pragma unroll 8
            for (int v = 0; v < 128; v++) acc += s_h[v] * Wm2[v*64 + u];
            acc *= RSQRT_MUL;
            s_radRaw[u] = acc;
            s_radB[u]   = acc * B0C;
            if (blockIdx.x == 0) out[OFF_RAD + g*64 + u] = acc;
        }
        BAR_FRONT();

        const float* Wa[6] = {Wa0, Wa1, Wa2, Wa3, Wa4, Wa5};
        for (int o = u; o < C_*KDIM; o += 128) {
            int k = o >> 2, c = o & 3;
            int l = lofk(k);
            const float* w = Wa[l];
            float acc = 0.f;
            #pragma unroll 8
            for (int v = 0; v < 128; v++) acc += s_sc[k][v] * w[v*4 + c];
            acc *= RSQRT_MUL;
            s_ang[c][k] = acc;

            if (blockIdx.x == 0) {
                float* lp = out + OFF_LPC + ((size_t)(g*C_ + c) * R_) * KDIM + k;
                if (k == 0) {
                    #pragma unroll 8
                    for (int r = 0; r < 64; r++) lp[r*KDIM] = acc + s_radRaw[r];
                } else {
                    #pragma unroll 8
                    for (int r = 0; r < 64; r++) lp[r*KDIM] = acc;
                }
            }
        }
    } else if (tid < 132) {
        // ----- NODE TEAM (warp 4, lanes 0-3): one GL root + F row each -----
        const int row = tid - 128;
        const int b = b0 + row;
        if (b < RB) {
            const int n = RB;
            int i = n - 1 - b;   // descending guess -> ascending y (numpy order)
            float xf = cosf(PI_F * (i + 0.75f) / (n + 0.5f));

            #pragma unroll 1
            for (int it = 0; it < 4; it++) {
                float pm = 1.0f, pc = xf;
                #pragma unroll 4
                for (int k = 2; k <= n; k++) {
                    float pn = fmaf(sca[k] * xf, pc, -scb[k] * pm);
                    pm = pc; pc = pn;
                }
                float dp = n * (xf * pc - pm) / (xf * xf - 1.0f);
                xf -= pc / dp;
            }

            // associated Legendre l<=5 (Condon-Shortley), float
            float y = xf;
            float somx2 = sqrtf(fmaxf(1.0f - y * y, 0.0f));
            float P[6][6];
            P[0][0] = 1.0f;
            #pragma unroll
            for (int m = 1; m <= 5; m++) P[m][m] = -(2.0f*m - 1.0f) * somx2 * P[m-1][m-1];
            #pragma unroll
            for (int m = 0; m < 5; m++)  P[m+1][m] = (2.0f*m + 1.0f) * y * P[m][m];
            #pragma unroll
            for (int m = 0; m <= 5; m++)
                #pragma unroll
                for (int l = m + 2; l <= 5; l++)
                    P[l][m] = ((2.0f*l - 1.0f) * y * P[l-1][m]
                               - (l + m - 1.0f) * P[l-2][m]) / (float)(l - m);

            float fact[11];
            fact[0] = 1.0f;
            #pragma unroll
            for (int q = 1; q <= 10; q++) fact[q] = fact[q-1] * q;

            #pragma unroll
            for (int l = 0; l <= 5; l++) {
                #pragma unroll
                for (int m = 0; m <= l; m++) {
                    float N = sqrtf((2.0f*l + 1.0f) / FOURPI_F * fact[l-m] / fact[l+m]);
                    if (m == 0) {
                        s_F[row][l*l + l] = N * P[l][0];
                    } else {
                        float v = 1.4142135623730951f * N * P[l][m];
                        s_F[row][l*l + l + m] = v;   // cos(m*alpha) partner
                        s_F[row][l*l + l - m] = v;   // sin(m*alpha) partner
                    }
                }
            }
        }
    }
    __syncthreads();

    // m-separation: A[row][c][j] = sum_l ang[c,k(l,ms)] * F[row,k(l,ms)], j=ms+5
    if (tid < 4 * C_ * MDIM) {
        int j   = tid % MDIM;
        int c   = (tid / MDIM) & 3;
        int row = tid / (MDIM * C_);
        float acc = 0.f;
        if (j < 11 && b0 + row < RB) {
            int ms = j - 5;
            int am = ms < 0 ? -ms : ms;
            #pragma unroll 1
            for (int l = am; l <= 5; l++) {
                int k = l*l + l + ms;
                acc += s_ang[c][k] * s_F[row][k];
            }
        }
        s_A[row][c][j] = acc;
    }
    __syncthreads();

    // ----- pixel loop: 4 consecutive pixels/thread, float4 streaming stores
    int p = p0 + tid;
    if (p >= NPIX4) return;

    const float4* A4 = (const float4*)&s_A[0][0][0];

    float lse4[4];
    #pragma unroll
    for (int s = 0; s < 4; s++) {
        int pix = 4*p + s;
        int b = pix / RA;
        int a = pix - b * RA;
        int row = b - b0;

        float c1, s1;
        float al = (float)((2.0 * 3.14159265358979323846 / (double)RA) * (double)a);
        __sincosf(al, &s1, &c1);
        float c2x = 2.f * c1;
        float cm2 = c2x*c1 - 1.f,  sm2 = c2x*s1;
        float cm3 = c2x*cm2 - c1,  sm3 = c2x*sm2 - s1;
        float cm4 = c2x*cm3 - cm2, sm4 = c2x*sm3 - sm2;
        float cm5 = c2x*cm4 - cm3, sm5 = c2x*sm4 - sm3;
        float t0 = sm5, t1 = sm4, t2 = sm3, t3 = sm2, t4 = s1;
        float t5 = 1.f, t6 = c1, t7 = cm2, t8 = cm3, t9 = cm4, t10 = cm5;

        float v[4];
        #pragma unroll
        for (int c = 0; c < 4; c++) {
            float4 a0 = A4[(row*4 + c)*3 + 0];
            float4 a1 = A4[(row*4 + c)*3 + 1];
            float4 a2 = A4[(row*4 + c)*3 + 2];
            float acc;
            acc = a0.x * t0;
            acc = fmaf(a0.y, t1, acc);
            acc = fmaf(a0.z, t2, acc);
            acc = fmaf(a0.w, t3, acc);
            acc = fmaf(a1.x, t4, acc);
            acc = fmaf(a1.y, t5, acc);
            acc = fmaf(a1.z, t6, acc);
            acc = fmaf(a1.w, t7, acc);
            acc = fmaf(a2.x, t8, acc);
            acc = fmaf(a2.y, t9, acc);
            acc = fmaf(a2.z, t10, acc);
            v[c] = acc;
        }
        float mx = fmaxf(fmaxf(v[0], v[1]), fmaxf(v[2], v[3]));
        lse4[s] = mx + __logf(__expf(v[0]-mx) + __expf(v[1]-mx)
                            + __expf(v[2]-mx) + __expf(v[3]-mx));
    }

    float4 L = make_float4(lse4[0], lse4[1], lse4[2], lse4[3]);
    __stcs((float4*)(out + OFF_ANG + (size_t)g * NPIX + 4*p), L);

    float* pp = out + OFF_POS + ((size_t)g * R_) * NPIX + 4*p;
    #pragma unroll 8
    for (int r = 0; r < R_; r++) {
        float rb = s_radB[r];
        __stcs((float4*)pp, make_float4(L.x + rb, L.y + rb, L.z + rb, L.w + rb));
        pp += NPIX;
    }
}

// ---------------------------------------------------------------------------
extern "C" void kernel_launch(void* const* d_in, const int* in_sizes, int n_in,
                              void* d_out, int out_size) {
    const float* emb  = (const float*)d_in[0];
    const float* spec = (const float*)d_in[1];
    const float* Wr   = (const float*)d_in[2];
    const float* Wm1  = (const float*)d_in[3];
    const float* Wm2  = (const float*)d_in[4];
    const float* Wa0  = (const float*)d_in[5];
    const float* Wa1  = (const float*)d_in[6];
    const float* Wa2  = (const float*)d_in[7];
    const float* Wa3  = (const float*)d_in[8];
    const float* Wa4  = (const float*)d_in[9];
    const float* Wa5  = (const float*)d_in[10];
    const int* focus  = (const int*)d_in[11];
    const int* tspec  = (const int*)d_in[12];
    float* out = (float*)d_out;

    dim3 gg((NPIX4 + 255) / 256, G_);
    k_all<<<gg, 256>>>(emb, spec, Wr, Wm1, Wm2,
                       Wa0, Wa1, Wa2, Wa3, Wa4, Wa5,
                       focus, tspec, out);
}

// round 7
// speedup vs baseline: 1.0805x; 1.0805x over previous
#include <cuda_runtime.h>
#include <cuda_bf16.h>
#include <math.h>

// ---------------------------------------------------------------------------
// Problem constants
// ---------------------------------------------------------------------------
#define G_      16
#define C_      4
#define R_      64
#define MUL_    128
#define KDIM    36          // (LMAX+1)^2
#define RB      180
#define RA      359
#define NPIX    (RB*RA)     // 64620
#define NPIX4   (NPIX/4)    // 16155
#define EMB     4608
#define NIRR    768
#define MDIM    12          // 11 signed-m slots (m=-5..5) + 1 pad
#define TGRP    512         // float4 groups per tile (2048 pixels)
#define NROWS   8           // max beta rows a tile can span (ceil(2048/359)+1=7)

#define RSQRT_MUL 0.08838834764831845f   // 1/sqrt(128)
#define RSQRT_RAD 0.125f                 // 1/sqrt(64)
#define B0C       0.28209479177387814f   // Y00 = 1/sqrt(4*pi)
#define PI_F      3.14159265358979323846f
#define FOURPI_F  12.566370614359172f

// output layout: concat of the 4 returned tensors, flattened, in order
#define OFF_LPC  0
#define OFF_POS  147456                          // 16*4*64*36
#define OFF_ANG  (OFF_POS + 66170880)            // + 16*64*64620
#define OFF_RAD  (OFF_ANG + 1033920)             // + 16*64620

// ---------------------------------------------------------------------------
// Device scratch
// ---------------------------------------------------------------------------
__device__ float g_F[RB][KDIM];      // beta SH factor (norm & sqrt2 included)
__device__ float g_ang[G_*C_*KDIM];  // angular coefficients
__device__ float g_rad[G_*R_];       // radial logits

__device__ __forceinline__ int lofk(int k) {
    const int t[36] = {0,1,1,1,2,2,2,2,2,3,3,3,3,3,3,3,
                       4,4,4,4,4,4,4,4,4,5,5,5,5,5,5,5,5,5,5,5};
    return t[k];
}

// ---------------------------------------------------------------------------
// K_setup: fused k_nodes (blocks 0..RB-1) + k_front (blocks RB..RB+G_-1).
// Float-only (no FP64 divides): tables + 3 Newton iters + float Legendre.
// ---------------------------------------------------------------------------
__device__ void nodes_body(int b) {
    __shared__ float sca[RB + 1], scb[RB + 1];

    const int n = RB;
    for (int k = 2 + threadIdx.x; k <= n; k += 128) {
        float kf = (float)k;
        sca[k] = (2.0f * kf - 1.0f) / kf;
        scb[k] = (kf - 1.0f) / kf;
    }
    __syncthreads();
    if (threadIdx.x != 0) return;

    int i = n - 1 - b;   // descending guess index -> ascending y (numpy order)
    float xf = cosf(PI_F * (i + 0.75f) / (n + 0.5f));

    #pragma unroll 1
    for (int it = 0; it < 3; it++) {
        float pm = 1.0f, pc = xf;
        #pragma unroll 4
        for (int k = 2; k <= n; k++) {
            float pn = fmaf(sca[k] * xf, pc, -scb[k] * pm);
            pm = pc; pc = pn;
        }
        float dp = n * (xf * pc - pm) / (xf * xf - 1.0f);
        xf -= pc / dp;
    }

    // associated Legendre l<=5 (Condon-Shortley), float
    float y = xf;
    float somx2 = sqrtf(fmaxf(1.0f - y * y, 0.0f));
    float P[6][6];
    P[0][0] = 1.0f;
    #pragma unroll
    for (int m = 1; m <= 5; m++) P[m][m] = -(2.0f*m - 1.0f) * somx2 * P[m-1][m-1];
    #pragma unroll
    for (int m = 0; m < 5; m++)  P[m+1][m] = (2.0f*m + 1.0f) * y * P[m][m];
    #pragma unroll
    for (int m = 0; m <= 5; m++)
        #pragma unroll
        for (int l = m + 2; l <= 5; l++)
            P[l][m] = ((2.0f*l - 1.0f) * y * P[l-1][m]
                       - (l + m - 1.0f) * P[l-2][m]) / (float)(l - m);

    float fact[11];
    fact[0] = 1.0f;
    #pragma unroll
    for (int q = 1; q <= 10; q++) fact[q] = fact[q-1] * q;

    #pragma unroll
    for (int l = 0; l <= 5; l++) {
        #pragma unroll
        for (int m = 0; m <= l; m++) {
            float N = sqrtf((2.0f*l + 1.0f) / FOURPI_F * fact[l-m] / fact[l+m]);
            if (m == 0) {
                g_F[b][l*l + l] = N * P[l][0];
            } else {
                float v = 1.4142135623730951f * N * P[l][m];
                g_F[b][l*l + l + m] = v;   // cos(m*alpha) partner
                g_F[b][l*l + l - m] = v;   // sin(m*alpha) partner
            }
        }
    }
}

__device__ void front_body(int g,
                           const float* __restrict__ emb,
                           const float* __restrict__ spec,
                           const float* __restrict__ Wr,
                           const float* __restrict__ Wm1,
                           const float* __restrict__ Wm2,
                           const float* const* Wa,
                           const int* __restrict__ focus,
                           const int* __restrict__ tspec,
                           float* __restrict__ out) {
    __shared__ float s_sc[KDIM][MUL_ + 1];
    __shared__ float s_r[64];
    __shared__ float s_h[128];
    __shared__ float s_rad[64];

    int u = threadIdx.x;
    const float* f  = emb  + (size_t)focus[g] * EMB;
    const float* sp = spec + (size_t)tspec[g] * NIRR;

    #pragma unroll
    for (int l = 0; l <= 5; l++) {
        float s = sp[128*l + u];
        int d = 2*l + 1;
        const float* fb = f + 128*l*l + u*d;
        for (int m = 0; m < d; m++) s_sc[l*l + m][u] = fb[m] * s;
    }
    __syncthreads();

    if (u < 64) {
        float acc = 0.f;
        #pragma unroll 8
        for (int v = 0; v < 128; v++) acc += s_sc[0][v] * Wr[v*64 + u];
        s_r[u] = acc * RSQRT_MUL;
    }
    __syncthreads();

    {
        float acc = 0.f;
        #pragma unroll 8
        for (int j = 0; j < 64; j++) acc += s_r[j] * Wm1[j*128 + u];
        acc *= RSQRT_RAD;
        s_h[u] = fmaxf(acc, 0.f) + log1pf(expf(-fabsf(acc)));
    }
    __syncthreads();

    if (u < 64) {
        float acc = 0.f;
        #pragma unroll 8
        for (int v = 0; v < 128; v++) acc += s_h[v] * Wm2[v*64 + u];
        acc *= RSQRT_MUL;
        s_rad[u] = acc;
        g_rad[g*64 + u] = acc;
        out[OFF_RAD + g*64 + u] = acc;
    }
    __syncthreads();

    for (int o = u; o < C_*KDIM; o += 128) {
        int k = o >> 2, c = o & 3;
        int l = lofk(k);
        const float* w = Wa[l];
        float acc = 0.f;
        #pragma unroll 8
        for (int v = 0; v < 128; v++) acc += s_sc[k][v] * w[v*4 + c];
        acc *= RSQRT_MUL;
        g_ang[(g*C_ + c)*KDIM + k] = acc;

        float* lp = out + OFF_LPC + ((size_t)(g*C_ + c) * R_) * KDIM + k;
        if (k == 0) {
            #pragma unroll 8
            for (int r = 0; r < 64; r++) lp[r*KDIM] = acc + s_rad[r];
        } else {
            #pragma unroll 8
            for (int r = 0; r < 64; r++) lp[r*KDIM] = acc;
        }
    }
}

__global__ void __launch_bounds__(128) k_setup(
        const float* __restrict__ emb, const float* __restrict__ spec,
        const float* __restrict__ Wr, const float* __restrict__ Wm1,
        const float* __restrict__ Wm2,
        const float* __restrict__ Wa0, const float* __restrict__ Wa1,
        const float* __restrict__ Wa2, const float* __restrict__ Wa3,
        const float* __restrict__ Wa4, const float* __restrict__ Wa5,
        const int* __restrict__ focus, const int* __restrict__ tspec,
        float* __restrict__ out) {
    if (blockIdx.x < RB) {
        nodes_body(blockIdx.x);
    } else {
        const float* Wa[6] = {Wa0, Wa1, Wa2, Wa3, Wa4, Wa5};
        front_body(blockIdx.x - RB, emb, spec, Wr, Wm1, Wm2, Wa, focus, tspec, out);
    }
}

// ---------------------------------------------------------------------------
// K_grid: tile = 2048 pixels (512 float4 groups) x 1 graph. Compute phase
// caches the tile's LSE values in smem; store phase writes 8KB CONTIGUOUS
// per r-plane per block (vs 512B/warp in R4 -> DRAM row-buffer friendly).
// grid = (32, 16), block = 256.
// ---------------------------------------------------------------------------
__global__ void __launch_bounds__(256) k_grid(float* __restrict__ out) {
    __shared__ __align__(16) float4 s_L[TGRP];        // tile LSE values (8KB)
    __shared__ __align__(16) float s_A[NROWS][C_][MDIM];
    __shared__ __align__(16) float s_F[NROWS][KDIM];
    __shared__ float s_ang[C_][KDIM];
    __shared__ float s_radB[R_];

    const int g   = blockIdx.y;
    const int gp0 = blockIdx.x * TGRP;               // first group of tile
    const int tid = threadIdx.x;
    const int b0  = (4 * gp0) / RA;

    // ---- prologue loads
    if (tid < C_*KDIM) s_ang[tid & 3][tid >> 2] = g_ang[g*C_*KDIM + ((tid & 3)*KDIM + (tid >> 2))];
    // simpler consistent mapping: load linear
    __syncthreads();
    if (tid < C_*KDIM) {           // overwrite with straightforward layout
        int c = tid / KDIM, k = tid - c*KDIM;
        s_ang[c][k] = g_ang[(g*C_ + c)*KDIM + k];
    }
    if (tid >= 192 && tid < 192 + R_) s_radB[tid - 192] = g_rad[g*R_ + (tid - 192)] * B0C;
    for (int o = tid; o < NROWS*KDIM; o += 256) {
        int row = o / KDIM, k = o - row*KDIM;
        int b = b0 + row;
        s_F[row][k] = (b < RB) ? g_F[b][k] : 0.f;
    }
    __syncthreads();

    // ---- m-separation: A[row][c][j] = sum_l ang[c,k(l,ms)]*F[row,k(l,ms)]
    for (int o = tid; o < NROWS*C_*MDIM; o += 256) {
        int j   = o % MDIM;
        int c   = (o / MDIM) & 3;
        int row = o / (MDIM * C_);
        float acc = 0.f;
        if (j < 11) {
            int ms = j - 5;
            int am = ms < 0 ? -ms : ms;
            #pragma unroll 1
            for (int l = am; l <= 5; l++) {
                int k = l*l + l + ms;
                acc += s_ang[c][k] * s_F[row][k];
            }
        }
        s_A[row][c][j] = acc;
    }
    __syncthreads();

    const float4* A4 = (const float4*)&s_A[0][0][0];

    // ---- compute phase: 2 groups per thread -> s_L
    #pragma unroll
    for (int jj = 0; jj < 2; jj++) {
        int grp = gp0 + tid + 256*jj;
        if (grp >= NPIX4) break;

        float lse4[4];
        #pragma unroll
        for (int s = 0; s < 4; s++) {
            int pix = 4*grp + s;
            int b = pix / RA;
            int a = pix - b * RA;
            int row = b - b0;

            float c1, s1;
            float al = (float)((2.0 * 3.14159265358979323846 / (double)RA) * (double)a);
            __sincosf(al, &s1, &c1);
            float c2x = 2.f * c1;
            float cm2 = c2x*c1 - 1.f,  sm2 = c2x*s1;
            float cm3 = c2x*cm2 - c1,  sm3 = c2x*sm2 - s1;
            float cm4 = c2x*cm3 - cm2, sm4 = c2x*sm3 - sm2;
            float cm5 = c2x*cm4 - cm3, sm5 = c2x*sm4 - sm3;
            float t0 = sm5, t1 = sm4, t2 = sm3, t3 = sm2, t4 = s1;
            float t5 = 1.f, t6 = c1, t7 = cm2, t8 = cm3, t9 = cm4, t10 = cm5;

            float v[4];
            #pragma unroll
            for (int c = 0; c < 4; c++) {
                float4 a0 = A4[(row*4 + c)*3 + 0];
                float4 a1 = A4[(row*4 + c)*3 + 1];
                float4 a2 = A4[(row*4 + c)*3 + 2];
                float acc;
                acc = a0.x * t0;
                acc = fmaf(a0.y, t1, acc);
                acc = fmaf(a0.z, t2, acc);
                acc = fmaf(a0.w, t3, acc);
                acc = fmaf(a1.x, t4, acc);
                acc = fmaf(a1.y, t5, acc);
                acc = fmaf(a1.z, t6, acc);
                acc = fmaf(a1.w, t7, acc);
                acc = fmaf(a2.x, t8, acc);
                acc = fmaf(a2.y, t9, acc);
                acc = fmaf(a2.z, t10, acc);
                v[c] = acc;
            }
            float mx = fmaxf(fmaxf(v[0], v[1]), fmaxf(v[2], v[3]));
            lse4[s] = mx + __logf(__expf(v[0]-mx) + __expf(v[1]-mx)
                                + __expf(v[2]-mx) + __expf(v[3]-mx));
        }
        s_L[tid + 256*jj] = make_float4(lse4[0], lse4[1], lse4[2], lse4[3]);
    }
    __syncthreads();

    // ---- store phase
    int grp0 = gp0 + tid;
    int grp1 = gp0 + tid + 256;
    bool v0 = (grp0 < NPIX4), v1 = (grp1 < NPIX4);
    float4 L0 = s_L[tid];
    float4 L1 = s_L[tid + 256];

    // angular_logits
    if (v0) __stcs((float4*)(out + OFF_ANG + (size_t)g * NPIX + 4*grp0), L0);
    if (v1) __stcs((float4*)(out + OFF_ANG + (size_t)g * NPIX + 4*grp1), L1);

    // position_logits: per r, block writes an 8KB contiguous span
    float* basep = out + OFF_POS + (size_t)g * R_ * NPIX;
    #pragma unroll 4
    for (int r = 0; r < R_; r++) {
        float rb = s_radB[r];
        float* pr = basep + (size_t)r * NPIX;
        if (v0) __stcs((float4*)(pr + 4*grp0),
                       make_float4(L0.x + rb, L0.y + rb, L0.z + rb, L0.w + rb));
        if (v1) __stcs((float4*)(pr + 4*grp1),
                       make_float4(L1.x + rb, L1.y + rb, L1.z + rb, L1.w + rb));
    }
}

// ---------------------------------------------------------------------------
extern "C" void kernel_launch(void* const* d_in, const int* in_sizes, int n_in,
                              void* d_out, int out_size) {
    const float* emb  = (const float*)d_in[0];
    const float* spec = (const float*)d_in[1];
    const float* Wr   = (const float*)d_in[2];
    const float* Wm1  = (const float*)d_in[3];
    const float* Wm2  = (const float*)d_in[4];
    const float* Wa0  = (const float*)d_in[5];
    const float* Wa1  = (const float*)d_in[6];
    const float* Wa2  = (const float*)d_in[7];
    const float* Wa3  = (const float*)d_in[8];
    const float* Wa4  = (const float*)d_in[9];
    const float* Wa5  = (const float*)d_in[10];
    const int* focus  = (const int*)d_in[11];
    const int* tspec  = (const int*)d_in[12];
    float* out = (float*)d_out;

    k_setup<<<RB + G_, 128>>>(emb, spec, Wr, Wm1, Wm2,
                              Wa0, Wa1, Wa2, Wa3, Wa4, Wa5,
                              focus, tspec, out);
    dim3 gg((NPIX4 + TGRP - 1) / TGRP, G_);
    k_grid<<<gg, 256>>>(out);
}

// round 8
// speedup vs baseline: 1.1495x; 1.0638x over previous
#include <cuda_runtime.h>
#include <cuda_bf16.h>
#include <math.h>

// ---------------------------------------------------------------------------
// Problem constants
// ---------------------------------------------------------------------------
#define G_      16
#define C_      4
#define R_      64
#define MUL_    128
#define KDIM    36          // (LMAX+1)^2
#define RB      180
#define RA      359
#define NPIX    (RB*RA)     // 64620
#define NPIX4   (NPIX/4)    // 16155
#define EMB     4608
#define NIRR    768
#define MDIM    12          // 11 signed-m slots (m=-5..5) + 1 pad

#define RSQRT_MUL 0.08838834764831845f   // 1/sqrt(128)
#define RSQRT_RAD 0.125f                 // 1/sqrt(64)
#define B0C       0.28209479177387814f   // Y00 = 1/sqrt(4*pi)
#define PI_F      3.14159265358979323846f
#define FOURPI_F  12.566370614359172f

// Tricomi constants for n = 180:
//   (n-1)/(8 n^3)  = 179/46,656,000
//   1/(384 n^4)    = 1/403,107,840,000... (384*180^4 = 4.031078e11)
#define TRIC1 3.8365912208504801e-06f
#define TRIC2 2.4807256e-12f

// output layout: concat of the 4 returned tensors, flattened, in order
#define OFF_LPC  0
#define OFF_POS  147456                          // 16*4*64*36
#define OFF_ANG  (OFF_POS + 66170880)            // + 16*64*64620
#define OFF_RAD  (OFF_ANG + 1033920)             // + 16*64620

// ---------------------------------------------------------------------------
// Device scratch
// ---------------------------------------------------------------------------
__device__ float g_F[RB][KDIM];      // beta SH factor (norm & sqrt2 included)
__device__ float g_ang[G_*C_*KDIM];  // angular coefficients
__device__ float g_rad[G_*R_];       // radial logits

__device__ __forceinline__ int lofk(int k) {
    const int t[36] = {0,1,1,1,2,2,2,2,2,3,3,3,3,3,3,3,
                       4,4,4,4,4,4,4,4,4,5,5,5,5,5,5,5,5,5,5,5};
    return t[k];
}

// ---------------------------------------------------------------------------
// Closed-form Gauss-Legendre node (Tricomi asymptotic, n=180) + normalized
// associated Legendre row -> g_F[b]. Pure float, ~60 flops, no serial chain.
// ---------------------------------------------------------------------------
__device__ void node_row(int b) {
    const int n = RB;
    int i = n - 1 - b;                       // ascending-y (numpy) ordering
    float th = PI_F * (i + 0.75f) / (n + 0.5f);
    float sth, cth;
    sincosf(th, &sth, &cth);
    float inv_s2 = 1.0f / (sth * sth);
    float y = (1.0f - TRIC1 - TRIC2 * (39.0f - 28.0f * inv_s2)) * cth;

    float somx2 = sqrtf(fmaxf(1.0f - y * y, 0.0f));
    float P[6][6];
    P[0][0] = 1.0f;
    #pragma unroll
    for (int m = 1; m <= 5; m++) P[m][m] = -(2.0f*m - 1.0f) * somx2 * P[m-1][m-1];
    #pragma unroll
    for (int m = 0; m < 5; m++)  P[m+1][m] = (2.0f*m + 1.0f) * y * P[m][m];
    #pragma unroll
    for (int m = 0; m <= 5; m++)
        #pragma unroll
        for (int l = m + 2; l <= 5; l++)
            P[l][m] = ((2.0f*l - 1.0f) * y * P[l-1][m]
                       - (l + m - 1.0f) * P[l-2][m]) / (float)(l - m);

    float fact[11];
    fact[0] = 1.0f;
    #pragma unroll
    for (int q = 1; q <= 10; q++) fact[q] = fact[q-1] * q;

    #pragma unroll
    for (int l = 0; l <= 5; l++) {
        #pragma unroll
        for (int m = 0; m <= l; m++) {
            float N = sqrtf((2.0f*l + 1.0f) / FOURPI_F * fact[l-m] / fact[l+m]);
            if (m == 0) {
                g_F[b][l*l + l] = N * P[l][0];
            } else {
                float v = 1.4142135623730951f * N * P[l][m];
                g_F[b][l*l + l + m] = v;   // cos(m*alpha) partner
                g_F[b][l*l + l - m] = v;   // sin(m*alpha) partner
            }
        }
    }
}

// ---------------------------------------------------------------------------
// Front section for one graph: gather, species scale, radial MLP, angular
// projections; emits log_position_coeffs + radial_logits. 128 threads.
// ---------------------------------------------------------------------------
__device__ void front_body(int g,
                           const float* __restrict__ emb,
                           const float* __restrict__ spec,
                           const float* __restrict__ Wr,
                           const float* __restrict__ Wm1,
                           const float* __restrict__ Wm2,
                           const float* const* Wa,
                           const int* __restrict__ focus,
                           const int* __restrict__ tspec,
                           float* __restrict__ out) {
    __shared__ float s_sc[KDIM][MUL_ + 1];
    __shared__ float s_r[64];
    __shared__ float s_h[128];
    __shared__ float s_rad[64];

    int u = threadIdx.x;
    const float* f  = emb  + (size_t)focus[g] * EMB;
    const float* sp = spec + (size_t)tspec[g] * NIRR;

    #pragma unroll
    for (int l = 0; l <= 5; l++) {
        float s = sp[128*l + u];
        int d = 2*l + 1;
        const float* fb = f + 128*l*l + u*d;
        for (int m = 0; m < d; m++) s_sc[l*l + m][u] = fb[m] * s;
    }
    __syncthreads();

    if (u < 64) {
        float acc = 0.f;
        #pragma unroll 8
        for (int v = 0; v < 128; v++) acc += s_sc[0][v] * Wr[v*64 + u];
        s_r[u] = acc * RSQRT_MUL;
    }
    __syncthreads();

    {
        float acc = 0.f;
        #pragma unroll 8
        for (int j = 0; j < 64; j++) acc += s_r[j] * Wm1[j*128 + u];
        acc *= RSQRT_RAD;
        s_h[u] = fmaxf(acc, 0.f) + log1pf(expf(-fabsf(acc)));
    }
    __syncthreads();

    if (u < 64) {
        float acc = 0.f;
        #pragma unroll 8
        for (int v = 0; v < 128; v++) acc += s_h[v] * Wm2[v*64 + u];
        acc *= RSQRT_MUL;
        s_rad[u] = acc;
        g_rad[g*64 + u] = acc;
        out[OFF_RAD + g*64 + u] = acc;
    }
    __syncthreads();

    for (int o = u; o < C_*KDIM; o += 128) {
        int k = o >> 2, c = o & 3;
        int l = lofk(k);
        const float* w = Wa[l];
        float acc = 0.f;
        #pragma unroll 8
        for (int v = 0; v < 128; v++) acc += s_sc[k][v] * w[v*4 + c];
        acc *= RSQRT_MUL;
        g_ang[(g*C_ + c)*KDIM + k] = acc;

        float* lp = out + OFF_LPC + ((size_t)(g*C_ + c) * R_) * KDIM + k;
        if (k == 0) {
            #pragma unroll 8
            for (int r = 0; r < 64; r++) lp[r*KDIM] = acc + s_rad[r];
        } else {
            #pragma unroll 8
            for (int r = 0; r < 64; r++) lp[r*KDIM] = acc;
        }
    }
}

// ---------------------------------------------------------------------------
// K_setup: blocks 0..15 = front per graph; block 16 = all 180 GL/Legendre
// rows (closed-form, embarrassingly parallel).
// ---------------------------------------------------------------------------
__global__ void __launch_bounds__(128) k_setup(
        const float* __restrict__ emb, const float* __restrict__ spec,
        const float* __restrict__ Wr, const float* __restrict__ Wm1,
        const float* __restrict__ Wm2,
        const float* __restrict__ Wa0, const float* __restrict__ Wa1,
        const float* __restrict__ Wa2, const float* __restrict__ Wa3,
        const float* __restrict__ Wa4, const float* __restrict__ Wa5,
        const int* __restrict__ focus, const int* __restrict__ tspec,
        float* __restrict__ out) {
    if (blockIdx.x < G_) {
        const float* Wa[6] = {Wa0, Wa1, Wa2, Wa3, Wa4, Wa5};
        front_body(blockIdx.x, emb, spec, Wr, Wm1, Wm2, Wa, focus, tspec, out);
    } else {
        for (int b = threadIdx.x; b < RB; b += 128) node_row(b);
    }
}

// ---------------------------------------------------------------------------
// K_grid (R4-proven version): per-block m-separation into A[4][C][12], then
// grid synthesis + LSE + radial broadcast. Thread = 4 consecutive pixels,
// blockIdx.y = graph. All heavy traffic = float4 streaming stores.
// ---------------------------------------------------------------------------
__global__ void __launch_bounds__(256) k_grid(float* __restrict__ out) {
    __shared__ __align__(16) float s_A[4][C_][MDIM];  // m-separated coeffs
    __shared__ float s_radB[R_];

    int g  = blockIdx.y;
    int p0 = blockIdx.x * 256;            // first 4-pixel group of this block
    int b0 = (4 * p0) / RA;               // first beta row touched

    if (threadIdx.x < R_) s_radB[threadIdx.x] = g_rad[g*R_ + threadIdx.x] * B0C;

    if (threadIdx.x < 4 * C_ * MDIM) {
        int j   = threadIdx.x % MDIM;
        int c   = (threadIdx.x / MDIM) & 3;
        int row = threadIdx.x / (MDIM * C_);
        int b   = b0 + row;
        float acc = 0.f;
        if (j < 11 && b < RB) {
            int ms = j - 5;
            int am = ms < 0 ? -ms : ms;
            const float* ag = &g_ang[(g*C_ + c) * KDIM];
            #pragma unroll 1
            for (int l = am; l <= 5; l++) {
                int k = l*l + l + ms;
                acc += ag[k] * g_F[b][k];
            }
        }
        s_A[row][c][j] = acc;
    }
    __syncthreads();

    int p = p0 + threadIdx.x;
    if (p >= NPIX4) return;

    const float4* A4 = (const float4*)&s_A[0][0][0];

    float lse4[4];
    #pragma unroll
    for (int s = 0; s < 4; s++) {
        int pix = 4*p + s;
        int b = pix / RA;
        int a = pix - b * RA;
        int row = b - b0;

        float c1, s1;
        float al = (float)((2.0 * 3.14159265358979323846 / (double)RA) * (double)a);
        __sincosf(al, &s1, &c1);
        float c2x = 2.f * c1;
        float cm2 = c2x*c1 - 1.f,  sm2 = c2x*s1;
        float cm3 = c2x*cm2 - c1,  sm3 = c2x*sm2 - s1;
        float cm4 = c2x*cm3 - cm2, sm4 = c2x*sm3 - sm2;
        float cm5 = c2x*cm4 - cm3, sm5 = c2x*sm4 - sm3;
        float t0 = sm5, t1 = sm4, t2 = sm3, t3 = sm2, t4 = s1;
        float t5 = 1.f, t6 = c1, t7 = cm2, t8 = cm3, t9 = cm4, t10 = cm5;

        float v[4];
        #pragma unroll
        for (int c = 0; c < 4; c++) {
            float4 a0 = A4[(row*4 + c)*3 + 0];
            float4 a1 = A4[(row*4 + c)*3 + 1];
            float4 a2 = A4[(row*4 + c)*3 + 2];
            float acc;
            acc = a0.x * t0;
            acc = fmaf(a0.y, t1, acc);
            acc = fmaf(a0.z, t2, acc);
            acc = fmaf(a0.w, t3, acc);
            acc = fmaf(a1.x, t4, acc);
            acc = fmaf(a1.y, t5, acc);
            acc = fmaf(a1.z, t6, acc);
            acc = fmaf(a1.w, t7, acc);
            acc = fmaf(a2.x, t8, acc);
            acc = fmaf(a2.y, t9, acc);
            acc = fmaf(a2.z, t10, acc);
            v[c] = acc;
        }
        float mx = fmaxf(fmaxf(v[0], v[1]), fmaxf(v[2], v[3]));
        lse4[s] = mx + __logf(__expf(v[0]-mx) + __expf(v[1]-mx)
                            + __expf(v[2]-mx) + __expf(v[3]-mx));
    }

    float4 L = make_float4(lse4[0], lse4[1], lse4[2], lse4[3]);
    __stcs((float4*)(out + OFF_ANG + (size_t)g * NPIX + 4*p), L);

    float* pp = out + OFF_POS + ((size_t)g * R_) * NPIX + 4*p;
    #pragma unroll 8
    for (int r = 0; r < R_; r++) {
        float rb = s_radB[r];
        __stcs((float4*)pp, make_float4(L.x + rb, L.y + rb, L.z + rb, L.w + rb));
        pp += NPIX;
    }
}

// ---------------------------------------------------------------------------
extern "C" void kernel_launch(void* const* d_in, const int* in_sizes, int n_in,
                              void* d_out, int out_size) {
    const float* emb  = (const float*)d_in[0];
    const float* spec = (const float*)d_in[1];
    const float* Wr   = (const float*)d_in[2];
    const float* Wm1  = (const float*)d_in[3];
    const float* Wm2  = (const float*)d_in[4];
    const float* Wa0  = (const float*)d_in[5];
    const float* Wa1  = (const float*)d_in[6];
    const float* Wa2  = (const float*)d_in[7];
    const float* Wa3  = (const float*)d_in[8];
    const float* Wa4  = (const float*)d_in[9];
    const float* Wa5  = (const float*)d_in[10];
    const int* focus  = (const int*)d_in[11];
    const int* tspec  = (const int*)d_in[12];
    float* out = (float*)d_out;

    k_setup<<<G_ + 1, 128>>>(emb, spec, Wr, Wm1, Wm2,
                             Wa0, Wa1, Wa2, Wa3, Wa4, Wa5,
                             focus, tspec, out);
    dim3 gg((NPIX4 + 255) / 256, G_);
    k_grid<<<gg, 256>>>(out);
}